// round 15
// baseline (speedup 1.0000x reference)
#include <cuda_runtime.h>
#include <cuda_bf16.h>
#include <cstdint>

// ---------------------------------------------------------------------------
// MultiHeadSelfAttention: B=4, N=2048, E=2048, H=3 full-width heads, fp32 ref.
// All GEMMs on warp-level mma.sync bf16 (m16n8k16), 3-term split precision:
//   C += A_hi*B_hi + A_hi*B_lo + A_lo*B_hi   (fp32 accumulators)
// Every GEMM is C[i,j] = sum_k A[i,k]*B[j,k], both operands K-major.
// R12: 4-stage x BK=16 cp.async pipeline, one __syncthreads per chunk,
//      256 threads, 2x4 warp grid (R13's 64x64 warp tile regressed; reverted).
// R14: cp.async store lane remap (lr=tid&127, lq=tid>>7). Old mapping
//      (lr=tid>>1) gave ~4-way smem bank conflicts on EVERY 16B async store
//      (16B-group (3r+q)%8 repeats within 8 lanes); new mapping makes 8
//      consecutive lanes hit groups 0,3,6,1,4,7,2,5 — conflict-free.
// ---------------------------------------------------------------------------

#define NE_   ((size_t)2048 * 2048)
#define BNE_  ((size_t)8192 * 2048)
#define HBNE_ ((size_t)3 * 8192 * 2048)

static __device__ __nv_bfloat16 g_xh[BNE_],  g_xl[BNE_];
static __device__ __nv_bfloat16 g_Wh[9 * NE_], g_Wl[9 * NE_];
static __device__ __nv_bfloat16 g_fwh[NE_], g_fwl[NE_];
static __device__ __nv_bfloat16 g_Qh[HBNE_], g_Ql[HBNE_];
static __device__ __nv_bfloat16 g_Kh[HBNE_], g_Kl[HBNE_];
static __device__ float         g_F[HBNE_];          // V fp32, then attn fp32
static __device__ __nv_bfloat16 g_Vth[HBNE_], g_Vtl[HBNE_];
static __device__ float         g_T[HBNE_];          // transposed scores
static __device__ __nv_bfloat16 g_Pth[HBNE_], g_Ptl[HBNE_];
static __device__ __nv_bfloat16 g_Mh[BNE_], g_Ml[BNE_];

// ------------------------------ PTX helpers --------------------------------

__device__ __forceinline__ uint32_t smem_u32(const void* p) {
    uint32_t a;
    asm("{ .reg .u64 t; cvta.to.shared.u64 t, %1; cvt.u32.u64 %0, t; }"
        : "=r"(a) : "l"(p));
    return a;
}
__device__ __forceinline__ void cp16(uint32_t d, const void* s) {
    asm volatile("cp.async.cg.shared.global [%0], [%1], 16;" :: "r"(d), "l"(s));
}
__device__ __forceinline__ void cp_commit() {
    asm volatile("cp.async.commit_group;");
}
__device__ __forceinline__ void cp_wait2() {
    asm volatile("cp.async.wait_group 2;");
}
__device__ __forceinline__ void cp_wait1() {
    asm volatile("cp.async.wait_group 1;");
}
__device__ __forceinline__ void cp_wait0() {
    asm volatile("cp.async.wait_group 0;");
}
__device__ __forceinline__ void ldm4(uint32_t* r, uint32_t addr) {
    asm volatile("ldmatrix.sync.aligned.m8n8.x4.shared.b16 {%0,%1,%2,%3}, [%4];"
                 : "=r"(r[0]), "=r"(r[1]), "=r"(r[2]), "=r"(r[3]) : "r"(addr));
}
__device__ __forceinline__ void mma16816(float* c, const uint32_t* a,
                                         const uint32_t* b) {
    asm volatile(
        "mma.sync.aligned.m16n8k16.row.col.f32.bf16.bf16.f32 "
        "{%0,%1,%2,%3}, {%4,%5,%6,%7}, {%8,%9}, {%0,%1,%2,%3};"
        : "+f"(c[0]), "+f"(c[1]), "+f"(c[2]), "+f"(c[3])
        : "r"(a[0]), "r"(a[1]), "r"(a[2]), "r"(a[3]), "r"(b[0]), "r"(b[1]));
}

// ------------------------------ GEMM kernel --------------------------------
// Tile 128x128, BK=16 per chunk, 128 chunks, K=2048, lda=ldb=ldc=2048.
// 256 threads = 8 warps in a 2x4 grid; warp tile 64x32.
// SMEM per stage: A_hi | A_lo | B_hi | B_lo, each 128 rows x 48B.
// 4 stages, prefetch distance 3, ONE __syncthreads per chunk.
// EPI: 0 = fp32 out, 1 = fp32 + bias, 2 = hi/lo bf16 out.

constexpr int PITCH = 48;                        // bytes per row (16-aligned)
constexpr int PART  = 128 * PITCH;               // 6144 B
constexpr int STAGE = 4 * PART;                  // 24576 B
constexpr int NSTG  = 4;
constexpr int SMEM_DYN = NSTG * STAGE;           // 98304 B (2 CTAs/SM)

template <int EPI>
__global__ __launch_bounds__(256, 2) void gemm_mma(
    const __nv_bfloat16* __restrict__ Ah, const __nv_bfloat16* __restrict__ Al,
    long long strideA,
    const __nv_bfloat16* __restrict__ Bh, const __nv_bfloat16* __restrict__ Bl,
    long long strideB,
    float* __restrict__ C, __nv_bfloat16* __restrict__ Ch,
    __nv_bfloat16* __restrict__ Cl, long long strideC,
    const float* __restrict__ bias)
{
    extern __shared__ __align__(16) char dynsmem[];
    const uint32_t sb = smem_u32(dynsmem);
    const int tid = threadIdx.x;
    const size_t z = blockIdx.z;
    const __nv_bfloat16* A0 = Ah + z * strideA;
    const __nv_bfloat16* A1 = Al + z * strideA;
    const __nv_bfloat16* B0 = Bh + z * strideB;
    const __nv_bfloat16* B1 = Bl + z * strideB;
    const int row0 = blockIdx.y * 128;
    const int col0 = blockIdx.x * 128;

    const int w = tid >> 5, l = tid & 31;
    const int wm = w & 1, wn = w >> 1;           // 2 x 4 warp grid

    // ldmatrix per-lane offsets (within a part), row pitch 48B
    const int rowA = wm * 64 + (l & 15);
    const uint32_t aoff = (uint32_t)rowA * PITCH + (l >> 4) * 16;
    const int rowB = wn * 32 + ((l >> 4) * 8) + (l & 7);
    const uint32_t boff = (uint32_t)rowB * PITCH + ((l >> 3) & 1) * 16;

    float acc[4][4][4];
#pragma unroll
    for (int i = 0; i < 4; i++)
#pragma unroll
        for (int j = 0; j < 4; j++)
#pragma unroll
            for (int e = 0; e < 4; e++) acc[i][j][e] = 0.f;

    // One chunk = 16 k-columns. Conflict-free store lane map: 8 consecutive
    // lanes hit rows r..r+7 at constant q -> 16B-groups (3r+q)%8 all distinct.
    const int lr = tid & 127, lq = tid >> 7;
    auto load_chunk = [&](int c, int s) {
        const uint32_t st = sb + s * STAGE;
        const int k0 = c * 16;
        const size_t ga = (size_t)(row0 + lr) * 2048 + k0 + lq * 8;
        const size_t gb = (size_t)(col0 + lr) * 2048 + k0 + lq * 8;
        const uint32_t so = (uint32_t)lr * PITCH + lq * 16;
        cp16(st + 0 * PART + so, A0 + ga);
        cp16(st + 1 * PART + so, A1 + ga);
        cp16(st + 2 * PART + so, B0 + gb);
        cp16(st + 3 * PART + so, B1 + gb);
        cp_commit();
    };

    load_chunk(0, 0);
    load_chunk(1, 1);
    load_chunk(2, 2);

    for (int c = 0; c < 128; c++) {
        if (c < 126) cp_wait2();
        else if (c == 126) cp_wait1();
        else cp_wait0();
        __syncthreads();                          // data visible + WAR guard
        const uint32_t st = sb + (c & 3) * STAGE;

        uint32_t ah[4][4], al2[4][4], bh[4][2], bl2[4][2];
#pragma unroll
        for (int mi = 0; mi < 4; mi++) {
            const uint32_t ad = aoff + (uint32_t)mi * 16 * PITCH;
            ldm4(ah[mi],  st + 0 * PART + ad);
            ldm4(al2[mi], st + 1 * PART + ad);
        }
#pragma unroll
        for (int n2 = 0; n2 < 2; n2++) {
            uint32_t t4[4];
            const uint32_t bd = boff + (uint32_t)n2 * 16 * PITCH;
            ldm4(t4, st + 2 * PART + bd);
            bh[2 * n2][0] = t4[0]; bh[2 * n2][1] = t4[1];
            bh[2 * n2 + 1][0] = t4[2]; bh[2 * n2 + 1][1] = t4[3];
            ldm4(t4, st + 3 * PART + bd);
            bl2[2 * n2][0] = t4[0]; bl2[2 * n2][1] = t4[1];
            bl2[2 * n2 + 1][0] = t4[2]; bl2[2 * n2 + 1][1] = t4[3];
        }
        // Term-grouped issue: same-accumulator reuses 4 MMAs apart.
#pragma unroll
        for (int mi = 0; mi < 4; mi++) {
#pragma unroll
            for (int ni = 0; ni < 4; ni++)
                mma16816(acc[mi][ni], ah[mi], bh[ni]);
#pragma unroll
            for (int ni = 0; ni < 4; ni++)
                mma16816(acc[mi][ni], ah[mi], bl2[ni]);
#pragma unroll
            for (int ni = 0; ni < 4; ni++)
                mma16816(acc[mi][ni], al2[mi], bh[ni]);
        }
        // Refill the stage freed at chunk c-1 (protected by this chunk's sync)
        if (c + 3 < 128) load_chunk(c + 3, (c + 3) & 3);
    }

    // ---- epilogue (register accumulators -> gmem) ----
    const int gid = l >> 2, tig = l & 3;
#pragma unroll
    for (int mi = 0; mi < 4; mi++) {
#pragma unroll
        for (int ni = 0; ni < 4; ni++) {
            const int row = row0 + wm * 64 + mi * 16 + gid;
            const int col = col0 + wn * 32 + ni * 8 + tig * 2;
            const float* cf = acc[mi][ni];
            if (EPI == 2) {
#pragma unroll
                for (int h = 0; h < 2; h++) {
                    const size_t o = z * strideC + (size_t)(row + 8 * h) * 2048 + col;
                    const float f0 = cf[2 * h], f1 = cf[2 * h + 1];
                    const __nv_bfloat16 h0 = __float2bfloat16(f0);
                    const __nv_bfloat16 h1 = __float2bfloat16(f1);
                    *reinterpret_cast<__nv_bfloat162*>(Ch + o) =
                        __halves2bfloat162(h0, h1);
                    *reinterpret_cast<__nv_bfloat162*>(Cl + o) =
                        __halves2bfloat162(
                            __float2bfloat16(f0 - __bfloat162float(h0)),
                            __float2bfloat16(f1 - __bfloat162float(h1)));
                }
            } else {
                float b0 = 0.f, b1 = 0.f;
                if (EPI == 1) { b0 = bias[col]; b1 = bias[col + 1]; }
#pragma unroll
                for (int h = 0; h < 2; h++) {
                    const size_t o = z * strideC + (size_t)(row + 8 * h) * 2048 + col;
                    *reinterpret_cast<float2*>(C + o) =
                        make_float2(cf[2 * h] + b0, cf[2 * h + 1] + b1);
                }
            }
        }
    }
}

// --------------------------- elementwise kernels ---------------------------

__global__ __launch_bounds__(256) void conv_hilo(
    const float4* __restrict__ in, __nv_bfloat162* __restrict__ hi,
    __nv_bfloat162* __restrict__ lo, size_t n4)
{
    for (size_t i = blockIdx.x * (size_t)blockDim.x + threadIdx.x; i < n4;
         i += (size_t)gridDim.x * blockDim.x) {
        const float4 v = in[i];
        const __nv_bfloat16 h0 = __float2bfloat16(v.x), h1 = __float2bfloat16(v.y);
        const __nv_bfloat16 h2 = __float2bfloat16(v.z), h3 = __float2bfloat16(v.w);
        hi[2 * i]     = __halves2bfloat162(h0, h1);
        hi[2 * i + 1] = __halves2bfloat162(h2, h3);
        lo[2 * i] = __halves2bfloat162(
            __float2bfloat16(v.x - __bfloat162float(h0)),
            __float2bfloat16(v.y - __bfloat162float(h1)));
        lo[2 * i + 1] = __halves2bfloat162(
            __float2bfloat16(v.z - __bfloat162float(h2)),
            __float2bfloat16(v.w - __bfloat162float(h3)));
    }
}

// Fused hi/lo conversion of the three per-head weight stacks (one launch).
__global__ __launch_bounds__(256) void conv_hilo3(
    const float4* __restrict__ in0, const float4* __restrict__ in1,
    const float4* __restrict__ in2, __nv_bfloat162* __restrict__ hi,
    __nv_bfloat162* __restrict__ lo)
{
    const size_t n4 = 3 * NE_ / 4;
    const float4* in = (blockIdx.y == 0) ? in0 : (blockIdx.y == 1) ? in1 : in2;
    __nv_bfloat162* h2p = hi + blockIdx.y * (3 * NE_ / 2);
    __nv_bfloat162* l2p = lo + blockIdx.y * (3 * NE_ / 2);
    for (size_t i = blockIdx.x * (size_t)blockDim.x + threadIdx.x; i < n4;
         i += (size_t)gridDim.x * blockDim.x) {
        const float4 v = in[i];
        const __nv_bfloat16 h0 = __float2bfloat16(v.x), h1 = __float2bfloat16(v.y);
        const __nv_bfloat16 h2 = __float2bfloat16(v.z), h3 = __float2bfloat16(v.w);
        h2p[2 * i]     = __halves2bfloat162(h0, h1);
        h2p[2 * i + 1] = __halves2bfloat162(h2, h3);
        l2p[2 * i] = __halves2bfloat162(
            __float2bfloat16(v.x - __bfloat162float(h0)),
            __float2bfloat16(v.y - __bfloat162float(h1)));
        l2p[2 * i + 1] = __halves2bfloat162(
            __float2bfloat16(v.z - __bfloat162float(h2)),
            __float2bfloat16(v.w - __bfloat162float(h3)));
    }
}

// Per-slab 2048x2048 transpose, fp32 in -> hi/lo bf16 out (transposed).
__global__ __launch_bounds__(256) void transpose_hilo(
    const float* __restrict__ in, __nv_bfloat16* __restrict__ hi,
    __nv_bfloat16* __restrict__ lo)
{
    __shared__ float t[32][33];
    const size_t z = blockIdx.z;
    const float* ip = in + z * NE_;
    __nv_bfloat16* oh = hi + z * NE_;
    __nv_bfloat16* ol = lo + z * NE_;
    const int x0 = blockIdx.x * 32, y0 = blockIdx.y * 32;
    const int tx = threadIdx.x & 31, ty = threadIdx.x >> 5;  // 32x8
#pragma unroll
    for (int i = 0; i < 4; i++)
        t[ty + 8 * i][tx] = ip[(size_t)(y0 + ty + 8 * i) * 2048 + x0 + tx];
    __syncthreads();
#pragma unroll
    for (int i = 0; i < 4; i++) {
        const float v = t[tx][ty + 8 * i];
        const __nv_bfloat16 h = __float2bfloat16(v);
        const size_t o = (size_t)(x0 + ty + 8 * i) * 2048 + y0 + tx;
        oh[o] = h;
        ol[o] = __float2bfloat16(v - __bfloat162float(h));
    }
}

// softmax over contiguous last axis (2048), scale folded into exp2
__global__ __launch_bounds__(256) void softmax_kernel(float* __restrict__ T, float c)
{
    __shared__ float red[8];
    float* p = T + (size_t)blockIdx.x * 2048;
    const int t = threadIdx.x;
    float x[8];
    {
        const float4 v0 = *reinterpret_cast<const float4*>(p + t * 8);
        const float4 v1 = *reinterpret_cast<const float4*>(p + t * 8 + 4);
        x[0] = v0.x; x[1] = v0.y; x[2] = v0.z; x[3] = v0.w;
        x[4] = v1.x; x[5] = v1.y; x[6] = v1.z; x[7] = v1.w;
    }
    float m = x[0];
#pragma unroll
    for (int j = 1; j < 8; j++) m = fmaxf(m, x[j]);
#pragma unroll
    for (int o = 16; o > 0; o >>= 1) m = fmaxf(m, __shfl_xor_sync(~0u, m, o));
    if ((t & 31) == 0) red[t >> 5] = m;
    __syncthreads();
    float bm = red[0];
#pragma unroll
    for (int i = 1; i < 8; i++) bm = fmaxf(bm, red[i]);
    __syncthreads();
    float e[8], s = 0.f;
#pragma unroll
    for (int j = 0; j < 8; j++) { e[j] = exp2f((x[j] - bm) * c); s += e[j]; }
#pragma unroll
    for (int o = 16; o > 0; o >>= 1) s += __shfl_xor_sync(~0u, s, o);
    if ((t & 31) == 0) red[t >> 5] = s;
    __syncthreads();
    float bs = red[0];
#pragma unroll
    for (int i = 1; i < 8; i++) bs += red[i];
    const float inv = 1.0f / bs;
    *reinterpret_cast<float4*>(p + t * 8) =
        make_float4(e[0] * inv, e[1] * inv, e[2] * inv, e[3] * inv);
    *reinterpret_cast<float4*>(p + t * 8 + 4) =
        make_float4(e[4] * inv, e[5] * inv, e[6] * inv, e[7] * inv);
}

// mean over 3 heads (slabs h*4+b), fp32 in -> hi/lo bf16 out
__global__ __launch_bounds__(256) void mean3_hilo(
    const float4* __restrict__ a, __nv_bfloat162* __restrict__ mh,
    __nv_bfloat162* __restrict__ ml)
{
    const float k = 1.0f / 3.0f;
    const size_t n4 = BNE_ / 4;
    for (size_t i = blockIdx.x * (size_t)blockDim.x + threadIdx.x; i < n4;
         i += (size_t)gridDim.x * blockDim.x) {
        const size_t elem = i * 4;
        const size_t b = elem >> 22, e = elem & (NE_ - 1);
        const size_t base4 = (b * NE_ + e) / 4;
        const float4 p = a[base4];
        const float4 q = a[base4 + NE_];
        const float4 r = a[base4 + 2 * NE_];
        float f0 = (p.x + q.x + r.x) * k, f1 = (p.y + q.y + r.y) * k;
        float f2 = (p.z + q.z + r.z) * k, f3 = (p.w + q.w + r.w) * k;
        const __nv_bfloat16 h0 = __float2bfloat16(f0), h1 = __float2bfloat16(f1);
        const __nv_bfloat16 h2 = __float2bfloat16(f2), h3 = __float2bfloat16(f3);
        mh[2 * i]     = __halves2bfloat162(h0, h1);
        mh[2 * i + 1] = __halves2bfloat162(h2, h3);
        ml[2 * i] = __halves2bfloat162(
            __float2bfloat16(f0 - __bfloat162float(h0)),
            __float2bfloat16(f1 - __bfloat162float(h1)));
        ml[2 * i + 1] = __halves2bfloat162(
            __float2bfloat16(f2 - __bfloat162float(h2)),
            __float2bfloat16(f3 - __bfloat162float(h3)));
    }
}

// ------------------------------- launcher ----------------------------------

extern "C" void kernel_launch(void* const* d_in, const int* in_sizes, int n_in,
                              void* d_out, int out_size)
{
    const float* x    = (const float*)d_in[0];
    const float* Wq   = (const float*)d_in[1];
    const float* Wk   = (const float*)d_in[2];
    const float* Wv   = (const float*)d_in[3];
    const float* fc_w = (const float*)d_in[4];
    const float* fc_b = (const float*)d_in[5];
    float* out = (float*)d_out;

    __nv_bfloat16 *xh, *xl, *Wh, *Wl, *fwh, *fwl, *Qh, *Ql, *Kh, *Kl;
    __nv_bfloat16 *Vth, *Vtl, *Pth, *Ptl, *Mh, *Ml;
    float *F, *T;
    cudaGetSymbolAddress((void**)&xh, g_xh);   cudaGetSymbolAddress((void**)&xl, g_xl);
    cudaGetSymbolAddress((void**)&Wh, g_Wh);   cudaGetSymbolAddress((void**)&Wl, g_Wl);
    cudaGetSymbolAddress((void**)&fwh, g_fwh); cudaGetSymbolAddress((void**)&fwl, g_fwl);
    cudaGetSymbolAddress((void**)&Qh, g_Qh);   cudaGetSymbolAddress((void**)&Ql, g_Ql);
    cudaGetSymbolAddress((void**)&Kh, g_Kh);   cudaGetSymbolAddress((void**)&Kl, g_Kl);
    cudaGetSymbolAddress((void**)&F, g_F);     cudaGetSymbolAddress((void**)&T, g_T);
    cudaGetSymbolAddress((void**)&Vth, g_Vth); cudaGetSymbolAddress((void**)&Vtl, g_Vtl);
    cudaGetSymbolAddress((void**)&Pth, g_Pth); cudaGetSymbolAddress((void**)&Ptl, g_Ptl);
    cudaGetSymbolAddress((void**)&Mh, g_Mh);   cudaGetSymbolAddress((void**)&Ml, g_Ml);

    cudaFuncSetAttribute(gemm_mma<0>, cudaFuncAttributeMaxDynamicSharedMemorySize, SMEM_DYN);
    cudaFuncSetAttribute(gemm_mma<1>, cudaFuncAttributeMaxDynamicSharedMemorySize, SMEM_DYN);
    cudaFuncSetAttribute(gemm_mma<2>, cudaFuncAttributeMaxDynamicSharedMemorySize, SMEM_DYN);

    const dim3 blk(256);
    // conversions: launches 0,1,2 (first gemm = launch 3; ncu -s 5 -> V proj)
    conv_hilo<<<2048, blk>>>((const float4*)x, (__nv_bfloat162*)xh,
                             (__nv_bfloat162*)xl, BNE_ / 4);
    {
        const dim3 g(1024, 3);
        conv_hilo3<<<g, blk>>>((const float4*)Wq, (const float4*)Wk,
                               (const float4*)Wv, (__nv_bfloat162*)Wh,
                               (__nv_bfloat162*)Wl);
    }
    conv_hilo<<<2048, blk>>>((const float4*)fc_w, (__nv_bfloat162*)fwh,
                             (__nv_bfloat162*)fwl, NE_ / 4);

    // projections (z = head): per-head weight slab stride is NE_
    {
        const dim3 g(16, 64, 3);
        gemm_mma<2><<<g, blk, SMEM_DYN>>>(xh, xl, 0, Wh, Wl, (long long)NE_,
                                          nullptr, Qh, Ql, (long long)BNE_, nullptr);
        gemm_mma<2><<<g, blk, SMEM_DYN>>>(xh, xl, 0, Wh + 3 * NE_, Wl + 3 * NE_,
                                          (long long)NE_, nullptr, Kh, Kl,
                                          (long long)BNE_, nullptr);
        gemm_mma<0><<<g, blk, SMEM_DYN>>>(xh, xl, 0, Wh + 6 * NE_, Wl + 6 * NE_,
                                          (long long)NE_, F, nullptr, nullptr,
                                          (long long)BNE_, nullptr);
    }
    // transposed scores: T[z][m][n] = sum_d K[m,d] Q[n,d], z = h*4+b
    {
        const dim3 g(16, 16, 12);
        gemm_mma<0><<<g, blk, SMEM_DYN>>>(Kh, Kl, (long long)NE_, Qh, Ql,
                                          (long long)NE_, T, nullptr, nullptr,
                                          (long long)NE_, nullptr);
    }
    // softmax over contiguous n, scale=1/sqrt(2048) in base-2
    softmax_kernel<<<12 * 2048, blk>>>(
        T, 0.022097086912079608f * 1.4426950408889634f);
    // transposes: P^T and V^T into hi/lo bf16
    {
        const dim3 g(64, 64, 12);
        transpose_hilo<<<g, blk>>>(T, Pth, Ptl);
        transpose_hilo<<<g, blk>>>(F, Vth, Vtl);
    }
    // attn[z][n][d] = sum_m Pt[n,m] Vt[d,m]  -> overwrite F
    {
        const dim3 g(16, 16, 12);
        gemm_mma<0><<<g, blk, SMEM_DYN>>>(Pth, Ptl, (long long)NE_, Vth, Vtl,
                                          (long long)NE_, F, nullptr, nullptr,
                                          (long long)NE_, nullptr);
    }
    // mean over heads -> hi/lo
    mean3_hilo<<<4096, blk>>>((const float4*)F, (__nv_bfloat162*)Mh,
                              (__nv_bfloat162*)Ml);
    // fc: out[m,e] = sum_d M[m,d] fw[e,d] + b[e]
    {
        const dim3 g(16, 64, 1);
        gemm_mma<1><<<g, blk, SMEM_DYN>>>(Mh, Ml, 0, fwh, fwl, 0, out, nullptr,
                                          nullptr, 0, fc_b);
    }
}

// round 16
// speedup vs baseline: 1.8237x; 1.8237x over previous
#include <cuda_runtime.h>
#include <cuda_bf16.h>
#include <cstdint>

// ---------------------------------------------------------------------------
// MultiHeadSelfAttention: B=4, N=2048, E=2048, H=3 full-width heads, fp32 ref.
// All GEMMs on warp-level mma.sync bf16 (m16n8k16), 3-term split precision:
//   C += A_hi*B_hi + A_hi*B_lo + A_lo*B_hi   (fp32 accumulators)
// Every GEMM is C[i,j] = sum_k A[i,k]*B[j,k], both operands K-major.
// R12: 4-stage x BK=16 cp.async pipeline, one __syncthreads per chunk,
//      256 threads, 2x4 warp grid. (R13 fat-warp and R14 lane-remap both
//      regressed and are reverted — R14 broke global coalescing.)
// R15: interleave LDSM with MMA inside the chunk: load B frags + A[0] after
//      the barrier, then prefetch A[mi+1] between MMA groups. Spreads the
//      post-barrier crossbar storm (768 XBar-cyc vs 768 tensor-cyc per
//      SM-chunk) across the MMA phase instead of serializing the two.
// ---------------------------------------------------------------------------

#define NE_   ((size_t)2048 * 2048)
#define BNE_  ((size_t)8192 * 2048)
#define HBNE_ ((size_t)3 * 8192 * 2048)

static __device__ __nv_bfloat16 g_xh[BNE_],  g_xl[BNE_];
static __device__ __nv_bfloat16 g_Wh[9 * NE_], g_Wl[9 * NE_];
static __device__ __nv_bfloat16 g_fwh[NE_], g_fwl[NE_];
static __device__ __nv_bfloat16 g_Qh[HBNE_], g_Ql[HBNE_];
static __device__ __nv_bfloat16 g_Kh[HBNE_], g_Kl[HBNE_];
static __device__ float         g_F[HBNE_];          // V fp32, then attn fp32
static __device__ __nv_bfloat16 g_Vth[HBNE_], g_Vtl[HBNE_];
static __device__ float         g_T[HBNE_];          // transposed scores
static __device__ __nv_bfloat16 g_Pth[HBNE_], g_Ptl[HBNE_];
static __device__ __nv_bfloat16 g_Mh[BNE_], g_Ml[BNE_];

// ------------------------------ PTX helpers --------------------------------

__device__ __forceinline__ uint32_t smem_u32(const void* p) {
    uint32_t a;
    asm("{ .reg .u64 t; cvta.to.shared.u64 t, %1; cvt.u32.u64 %0, t; }"
        : "=r"(a) : "l"(p));
    return a;
}
__device__ __forceinline__ void cp16(uint32_t d, const void* s) {
    asm volatile("cp.async.cg.shared.global [%0], [%1], 16;" :: "r"(d), "l"(s));
}
__device__ __forceinline__ void cp_commit() {
    asm volatile("cp.async.commit_group;");
}
__device__ __forceinline__ void cp_wait2() {
    asm volatile("cp.async.wait_group 2;");
}
__device__ __forceinline__ void cp_wait1() {
    asm volatile("cp.async.wait_group 1;");
}
__device__ __forceinline__ void cp_wait0() {
    asm volatile("cp.async.wait_group 0;");
}
__device__ __forceinline__ void ldm4(uint32_t* r, uint32_t addr) {
    asm volatile("ldmatrix.sync.aligned.m8n8.x4.shared.b16 {%0,%1,%2,%3}, [%4];"
                 : "=r"(r[0]), "=r"(r[1]), "=r"(r[2]), "=r"(r[3]) : "r"(addr));
}
__device__ __forceinline__ void mma16816(float* c, const uint32_t* a,
                                         const uint32_t* b) {
    asm volatile(
        "mma.sync.aligned.m16n8k16.row.col.f32.bf16.bf16.f32 "
        "{%0,%1,%2,%3}, {%4,%5,%6,%7}, {%8,%9}, {%0,%1,%2,%3};"
        : "+f"(c[0]), "+f"(c[1]), "+f"(c[2]), "+f"(c[3])
        : "r"(a[0]), "r"(a[1]), "r"(a[2]), "r"(a[3]), "r"(b[0]), "r"(b[1]));
}

// ------------------------------ GEMM kernel --------------------------------
// Tile 128x128, BK=16 per chunk, 128 chunks, K=2048, lda=ldb=ldc=2048.
// 256 threads = 8 warps in a 2x4 grid; warp tile 64x32.
// SMEM per stage: A_hi | A_lo | B_hi | B_lo, each 128 rows x 48B.
// 4 stages, prefetch distance 3, ONE __syncthreads per chunk.
// EPI: 0 = fp32 out, 1 = fp32 + bias, 2 = hi/lo bf16 out.

constexpr int PITCH = 48;                        // bytes per row (16-aligned)
constexpr int PART  = 128 * PITCH;               // 6144 B
constexpr int STAGE = 4 * PART;                  // 24576 B
constexpr int NSTG  = 4;
constexpr int SMEM_DYN = NSTG * STAGE;           // 98304 B (2 CTAs/SM)

template <int EPI>
__global__ __launch_bounds__(256, 2) void gemm_mma(
    const __nv_bfloat16* __restrict__ Ah, const __nv_bfloat16* __restrict__ Al,
    long long strideA,
    const __nv_bfloat16* __restrict__ Bh, const __nv_bfloat16* __restrict__ Bl,
    long long strideB,
    float* __restrict__ C, __nv_bfloat16* __restrict__ Ch,
    __nv_bfloat16* __restrict__ Cl, long long strideC,
    const float* __restrict__ bias)
{
    extern __shared__ __align__(16) char dynsmem[];
    const uint32_t sb = smem_u32(dynsmem);
    const int tid = threadIdx.x;
    const size_t z = blockIdx.z;
    const __nv_bfloat16* A0 = Ah + z * strideA;
    const __nv_bfloat16* A1 = Al + z * strideA;
    const __nv_bfloat16* B0 = Bh + z * strideB;
    const __nv_bfloat16* B1 = Bl + z * strideB;
    const int row0 = blockIdx.y * 128;
    const int col0 = blockIdx.x * 128;

    const int w = tid >> 5, l = tid & 31;
    const int wm = w & 1, wn = w >> 1;           // 2 x 4 warp grid

    // ldmatrix per-lane offsets (within a part), row pitch 48B
    const int rowA = wm * 64 + (l & 15);
    const uint32_t aoff = (uint32_t)rowA * PITCH + (l >> 4) * 16;
    const int rowB = wn * 32 + ((l >> 4) * 8) + (l & 7);
    const uint32_t boff = (uint32_t)rowB * PITCH + ((l >> 3) & 1) * 16;

    float acc[4][4][4];
#pragma unroll
    for (int i = 0; i < 4; i++)
#pragma unroll
        for (int j = 0; j < 4; j++)
#pragma unroll
            for (int e = 0; e < 4; e++) acc[i][j][e] = 0.f;

    // One chunk = 16 k-columns; lane pairs load adjacent 16B of one row
    // (R12 map: global-coalesced; R14's remap broke coalescing and is reverted)
    const int lr = tid >> 1, lq = tid & 1;
    auto load_chunk = [&](int c, int s) {
        const uint32_t st = sb + s * STAGE;
        const int k0 = c * 16;
        const size_t ga = (size_t)(row0 + lr) * 2048 + k0 + lq * 8;
        const size_t gb = (size_t)(col0 + lr) * 2048 + k0 + lq * 8;
        const uint32_t so = (uint32_t)lr * PITCH + lq * 16;
        cp16(st + 0 * PART + so, A0 + ga);
        cp16(st + 1 * PART + so, A1 + ga);
        cp16(st + 2 * PART + so, B0 + gb);
        cp16(st + 3 * PART + so, B1 + gb);
        cp_commit();
    };

    load_chunk(0, 0);
    load_chunk(1, 1);
    load_chunk(2, 2);

    for (int c = 0; c < 128; c++) {
        if (c < 126) cp_wait2();
        else if (c == 126) cp_wait1();
        else cp_wait0();
        __syncthreads();                          // data visible + WAR guard
        const uint32_t st = sb + (c & 3) * STAGE;

        uint32_t ah[4][4], al2[4][4], bh[4][2], bl2[4][2];
        // B fragments + A[0] up front (6 LDSM), A[mi+1] interleaved below.
#pragma unroll
        for (int n2 = 0; n2 < 2; n2++) {
            uint32_t t4[4];
            const uint32_t bd = boff + (uint32_t)n2 * 16 * PITCH;
            ldm4(t4, st + 2 * PART + bd);
            bh[2 * n2][0] = t4[0]; bh[2 * n2][1] = t4[1];
            bh[2 * n2 + 1][0] = t4[2]; bh[2 * n2 + 1][1] = t4[3];
            ldm4(t4, st + 3 * PART + bd);
            bl2[2 * n2][0] = t4[0]; bl2[2 * n2][1] = t4[1];
            bl2[2 * n2 + 1][0] = t4[2]; bl2[2 * n2 + 1][1] = t4[3];
        }
        ldm4(ah[0],  st + 0 * PART + aoff);
        ldm4(al2[0], st + 1 * PART + aoff);
#pragma unroll
        for (int mi = 0; mi < 4; mi++) {
            if (mi < 3) {                        // prefetch next A group
                const uint32_t ad = aoff + (uint32_t)(mi + 1) * 16 * PITCH;
                ldm4(ah[mi + 1],  st + 0 * PART + ad);
                ldm4(al2[mi + 1], st + 1 * PART + ad);
            }
            // Term-grouped issue: same-accumulator reuses 4 MMAs apart.
#pragma unroll
            for (int ni = 0; ni < 4; ni++)
                mma16816(acc[mi][ni], ah[mi], bh[ni]);
#pragma unroll
            for (int ni = 0; ni < 4; ni++)
                mma16816(acc[mi][ni], ah[mi], bl2[ni]);
#pragma unroll
            for (int ni = 0; ni < 4; ni++)
                mma16816(acc[mi][ni], al2[mi], bh[ni]);
        }
        // Refill the stage freed at chunk c-1 (protected by this chunk's sync)
        if (c + 3 < 128) load_chunk(c + 3, (c + 3) & 3);
    }

    // ---- epilogue (register accumulators -> gmem) ----
    const int gid = l >> 2, tig = l & 3;
#pragma unroll
    for (int mi = 0; mi < 4; mi++) {
#pragma unroll
        for (int ni = 0; ni < 4; ni++) {
            const int row = row0 + wm * 64 + mi * 16 + gid;
            const int col = col0 + wn * 32 + ni * 8 + tig * 2;
            const float* cf = acc[mi][ni];
            if (EPI == 2) {
#pragma unroll
                for (int h = 0; h < 2; h++) {
                    const size_t o = z * strideC + (size_t)(row + 8 * h) * 2048 + col;
                    const float f0 = cf[2 * h], f1 = cf[2 * h + 1];
                    const __nv_bfloat16 h0 = __float2bfloat16(f0);
                    const __nv_bfloat16 h1 = __float2bfloat16(f1);
                    *reinterpret_cast<__nv_bfloat162*>(Ch + o) =
                        __halves2bfloat162(h0, h1);
                    *reinterpret_cast<__nv_bfloat162*>(Cl + o) =
                        __halves2bfloat162(
                            __float2bfloat16(f0 - __bfloat162float(h0)),
                            __float2bfloat16(f1 - __bfloat162float(h1)));
                }
            } else {
                float b0 = 0.f, b1 = 0.f;
                if (EPI == 1) { b0 = bias[col]; b1 = bias[col + 1]; }
#pragma unroll
                for (int h = 0; h < 2; h++) {
                    const size_t o = z * strideC + (size_t)(row + 8 * h) * 2048 + col;
                    *reinterpret_cast<float2*>(C + o) =
                        make_float2(cf[2 * h] + b0, cf[2 * h + 1] + b1);
                }
            }
        }
    }
}

// --------------------------- elementwise kernels ---------------------------

__global__ __launch_bounds__(256) void conv_hilo(
    const float4* __restrict__ in, __nv_bfloat162* __restrict__ hi,
    __nv_bfloat162* __restrict__ lo, size_t n4)
{
    for (size_t i = blockIdx.x * (size_t)blockDim.x + threadIdx.x; i < n4;
         i += (size_t)gridDim.x * blockDim.x) {
        const float4 v = in[i];
        const __nv_bfloat16 h0 = __float2bfloat16(v.x), h1 = __float2bfloat16(v.y);
        const __nv_bfloat16 h2 = __float2bfloat16(v.z), h3 = __float2bfloat16(v.w);
        hi[2 * i]     = __halves2bfloat162(h0, h1);
        hi[2 * i + 1] = __halves2bfloat162(h2, h3);
        lo[2 * i] = __halves2bfloat162(
            __float2bfloat16(v.x - __bfloat162float(h0)),
            __float2bfloat16(v.y - __bfloat162float(h1)));
        lo[2 * i + 1] = __halves2bfloat162(
            __float2bfloat16(v.z - __bfloat162float(h2)),
            __float2bfloat16(v.w - __bfloat162float(h3)));
    }
}

// Fused hi/lo conversion of the three per-head weight stacks (one launch).
__global__ __launch_bounds__(256) void conv_hilo3(
    const float4* __restrict__ in0, const float4* __restrict__ in1,
    const float4* __restrict__ in2, __nv_bfloat162* __restrict__ hi,
    __nv_bfloat162* __restrict__ lo)
{
    const size_t n4 = 3 * NE_ / 4;
    const float4* in = (blockIdx.y == 0) ? in0 : (blockIdx.y == 1) ? in1 : in2;
    __nv_bfloat162* h2p = hi + blockIdx.y * (3 * NE_ / 2);
    __nv_bfloat162* l2p = lo + blockIdx.y * (3 * NE_ / 2);
    for (size_t i = blockIdx.x * (size_t)blockDim.x + threadIdx.x; i < n4;
         i += (size_t)gridDim.x * blockDim.x) {
        const float4 v = in[i];
        const __nv_bfloat16 h0 = __float2bfloat16(v.x), h1 = __float2bfloat16(v.y);
        const __nv_bfloat16 h2 = __float2bfloat16(v.z), h3 = __float2bfloat16(v.w);
        h2p[2 * i]     = __halves2bfloat162(h0, h1);
        h2p[2 * i + 1] = __halves2bfloat162(h2, h3);
        l2p[2 * i] = __halves2bfloat162(
            __float2bfloat16(v.x - __bfloat162float(h0)),
            __float2bfloat16(v.y - __bfloat162float(h1)));
        l2p[2 * i + 1] = __halves2bfloat162(
            __float2bfloat16(v.z - __bfloat162float(h2)),
            __float2bfloat16(v.w - __bfloat162float(h3)));
    }
}

// Per-slab 2048x2048 transpose, fp32 in -> hi/lo bf16 out (transposed).
__global__ __launch_bounds__(256) void transpose_hilo(
    const float* __restrict__ in, __nv_bfloat16* __restrict__ hi,
    __nv_bfloat16* __restrict__ lo)
{
    __shared__ float t[32][33];
    const size_t z = blockIdx.z;
    const float* ip = in + z * NE_;
    __nv_bfloat16* oh = hi + z * NE_;
    __nv_bfloat16* ol = lo + z * NE_;
    const int x0 = blockIdx.x * 32, y0 = blockIdx.y * 32;
    const int tx = threadIdx.x & 31, ty = threadIdx.x >> 5;  // 32x8
#pragma unroll
    for (int i = 0; i < 4; i++)
        t[ty + 8 * i][tx] = ip[(size_t)(y0 + ty + 8 * i) * 2048 + x0 + tx];
    __syncthreads();
#pragma unroll
    for (int i = 0; i < 4; i++) {
        const float v = t[tx][ty + 8 * i];
        const __nv_bfloat16 h = __float2bfloat16(v);
        const size_t o = (size_t)(x0 + ty + 8 * i) * 2048 + y0 + tx;
        oh[o] = h;
        ol[o] = __float2bfloat16(v - __bfloat162float(h));
    }
}

// softmax over contiguous last axis (2048), scale folded into exp2
__global__ __launch_bounds__(256) void softmax_kernel(float* __restrict__ T, float c)
{
    __shared__ float red[8];
    float* p = T + (size_t)blockIdx.x * 2048;
    const int t = threadIdx.x;
    float x[8];
    {
        const float4 v0 = *reinterpret_cast<const float4*>(p + t * 8);
        const float4 v1 = *reinterpret_cast<const float4*>(p + t * 8 + 4);
        x[0] = v0.x; x[1] = v0.y; x[2] = v0.z; x[3] = v0.w;
        x[4] = v1.x; x[5] = v1.y; x[6] = v1.z; x[7] = v1.w;
    }
    float m = x[0];
#pragma unroll
    for (int j = 1; j < 8; j++) m = fmaxf(m, x[j]);
#pragma unroll
    for (int o = 16; o > 0; o >>= 1) m = fmaxf(m, __shfl_xor_sync(~0u, m, o));
    if ((t & 31) == 0) red[t >> 5] = m;
    __syncthreads();
    float bm = red[0];
#pragma unroll
    for (int i = 1; i < 8; i++) bm = fmaxf(bm, red[i]);
    __syncthreads();
    float e[8], s = 0.f;
#pragma unroll
    for (int j = 0; j < 8; j++) { e[j] = exp2f((x[j] - bm) * c); s += e[j]; }
#pragma unroll
    for (int o = 16; o > 0; o >>= 1) s += __shfl_xor_sync(~0u, s, o);
    if ((t & 31) == 0) red[t >> 5] = s;
    __syncthreads();
    float bs = red[0];
#pragma unroll
    for (int i = 1; i < 8; i++) bs += red[i];
    const float inv = 1.0f / bs;
    *reinterpret_cast<float4*>(p + t * 8) =
        make_float4(e[0] * inv, e[1] * inv, e[2] * inv, e[3] * inv);
    *reinterpret_cast<float4*>(p + t * 8 + 4) =
        make_float4(e[4] * inv, e[5] * inv, e[6] * inv, e[7] * inv);
}

// mean over 3 heads (slabs h*4+b), fp32 in -> hi/lo bf16 out
__global__ __launch_bounds__(256) void mean3_hilo(
    const float4* __restrict__ a, __nv_bfloat162* __restrict__ mh,
    __nv_bfloat162* __restrict__ ml)
{
    const float k = 1.0f / 3.0f;
    const size_t n4 = BNE_ / 4;
    for (size_t i = blockIdx.x * (size_t)blockDim.x + threadIdx.x; i < n4;
         i += (size_t)gridDim.x * blockDim.x) {
        const size_t elem = i * 4;
        const size_t b = elem >> 22, e = elem & (NE_ - 1);
        const size_t base4 = (b * NE_ + e) / 4;
        const float4 p = a[base4];
        const float4 q = a[base4 + NE_];
        const float4 r = a[base4 + 2 * NE_];
        float f0 = (p.x + q.x + r.x) * k, f1 = (p.y + q.y + r.y) * k;
        float f2 = (p.z + q.z + r.z) * k, f3 = (p.w + q.w + r.w) * k;
        const __nv_bfloat16 h0 = __float2bfloat16(f0), h1 = __float2bfloat16(f1);
        const __nv_bfloat16 h2 = __float2bfloat16(f2), h3 = __float2bfloat16(f3);
        mh[2 * i]     = __halves2bfloat162(h0, h1);
        mh[2 * i + 1] = __halves2bfloat162(h2, h3);
        ml[2 * i] = __halves2bfloat162(
            __float2bfloat16(f0 - __bfloat162float(h0)),
            __float2bfloat16(f1 - __bfloat162float(h1)));
        ml[2 * i + 1] = __halves2bfloat162(
            __float2bfloat16(f2 - __bfloat162float(h2)),
            __float2bfloat16(f3 - __bfloat162float(h3)));
    }
}

// ------------------------------- launcher ----------------------------------

extern "C" void kernel_launch(void* const* d_in, const int* in_sizes, int n_in,
                              void* d_out, int out_size)
{
    const float* x    = (const float*)d_in[0];
    const float* Wq   = (const float*)d_in[1];
    const float* Wk   = (const float*)d_in[2];
    const float* Wv   = (const float*)d_in[3];
    const float* fc_w = (const float*)d_in[4];
    const float* fc_b = (const float*)d_in[5];
    float* out = (float*)d_out;

    __nv_bfloat16 *xh, *xl, *Wh, *Wl, *fwh, *fwl, *Qh, *Ql, *Kh, *Kl;
    __nv_bfloat16 *Vth, *Vtl, *Pth, *Ptl, *Mh, *Ml;
    float *F, *T;
    cudaGetSymbolAddress((void**)&xh, g_xh);   cudaGetSymbolAddress((void**)&xl, g_xl);
    cudaGetSymbolAddress((void**)&Wh, g_Wh);   cudaGetSymbolAddress((void**)&Wl, g_Wl);
    cudaGetSymbolAddress((void**)&fwh, g_fwh); cudaGetSymbolAddress((void**)&fwl, g_fwl);
    cudaGetSymbolAddress((void**)&Qh, g_Qh);   cudaGetSymbolAddress((void**)&Ql, g_Ql);
    cudaGetSymbolAddress((void**)&Kh, g_Kh);   cudaGetSymbolAddress((void**)&Kl, g_Kl);
    cudaGetSymbolAddress((void**)&F, g_F);     cudaGetSymbolAddress((void**)&T, g_T);
    cudaGetSymbolAddress((void**)&Vth, g_Vth); cudaGetSymbolAddress((void**)&Vtl, g_Vtl);
    cudaGetSymbolAddress((void**)&Pth, g_Pth); cudaGetSymbolAddress((void**)&Ptl, g_Ptl);
    cudaGetSymbolAddress((void**)&Mh, g_Mh);   cudaGetSymbolAddress((void**)&Ml, g_Ml);

    cudaFuncSetAttribute(gemm_mma<0>, cudaFuncAttributeMaxDynamicSharedMemorySize, SMEM_DYN);
    cudaFuncSetAttribute(gemm_mma<1>, cudaFuncAttributeMaxDynamicSharedMemorySize, SMEM_DYN);
    cudaFuncSetAttribute(gemm_mma<2>, cudaFuncAttributeMaxDynamicSharedMemorySize, SMEM_DYN);

    const dim3 blk(256);
    // conversions: launches 0,1,2 (first gemm = launch 3; ncu -s 5 -> V proj)
    conv_hilo<<<2048, blk>>>((const float4*)x, (__nv_bfloat162*)xh,
                             (__nv_bfloat162*)xl, BNE_ / 4);
    {
        const dim3 g(1024, 3);
        conv_hilo3<<<g, blk>>>((const float4*)Wq, (const float4*)Wk,
                               (const float4*)Wv, (__nv_bfloat162*)Wh,
                               (__nv_bfloat162*)Wl);
    }
    conv_hilo<<<2048, blk>>>((const float4*)fc_w, (__nv_bfloat162*)fwh,
                             (__nv_bfloat162*)fwl, NE_ / 4);

    // projections (z = head): per-head weight slab stride is NE_
    {
        const dim3 g(16, 64, 3);
        gemm_mma<2><<<g, blk, SMEM_DYN>>>(xh, xl, 0, Wh, Wl, (long long)NE_,
                                          nullptr, Qh, Ql, (long long)BNE_, nullptr);
        gemm_mma<2><<<g, blk, SMEM_DYN>>>(xh, xl, 0, Wh + 3 * NE_, Wl + 3 * NE_,
                                          (long long)NE_, nullptr, Kh, Kl,
                                          (long long)BNE_, nullptr);
        gemm_mma<0><<<g, blk, SMEM_DYN>>>(xh, xl, 0, Wh + 6 * NE_, Wl + 6 * NE_,
                                          (long long)NE_, F, nullptr, nullptr,
                                          (long long)BNE_, nullptr);
    }
    // transposed scores: T[z][m][n] = sum_d K[m,d] Q[n,d], z = h*4+b
    {
        const dim3 g(16, 16, 12);
        gemm_mma<0><<<g, blk, SMEM_DYN>>>(Kh, Kl, (long long)NE_, Qh, Ql,
                                          (long long)NE_, T, nullptr, nullptr,
                                          (long long)NE_, nullptr);
    }
    // softmax over contiguous n, scale=1/sqrt(2048) in base-2
    softmax_kernel<<<12 * 2048, blk>>>(
        T, 0.022097086912079608f * 1.4426950408889634f);
    // transposes: P^T and V^T into hi/lo bf16
    {
        const dim3 g(64, 64, 12);
        transpose_hilo<<<g, blk>>>(T, Pth, Ptl);
        transpose_hilo<<<g, blk>>>(F, Vth, Vtl);
    }
    // attn[z][n][d] = sum_m Pt[n,m] Vt[d,m]  -> overwrite F
    {
        const dim3 g(16, 16, 12);
        gemm_mma<0><<<g, blk, SMEM_DYN>>>(Pth, Ptl, (long long)NE_, Vth, Vtl,
                                          (long long)NE_, F, nullptr, nullptr,
                                          (long long)NE_, nullptr);
    }
    // mean over heads -> hi/lo
    mean3_hilo<<<4096, blk>>>((const float4*)F, (__nv_bfloat162*)Mh,
                              (__nv_bfloat162*)Ml);
    // fc: out[m,e] = sum_d M[m,d] fw[e,d] + b[e]
    {
        const dim3 g(16, 64, 1);
        gemm_mma<1><<<g, blk, SMEM_DYN>>>(Mh, Ml, 0, fwh, fwl, 0, out, nullptr,
                                          nullptr, 0, fc_b);
    }
}